// round 13
// baseline (speedup 1.0000x reference)
#include <cuda_runtime.h>

// SinkhornEvalKBestAbs — champion structure; final policy-matrix cell A/B:
// ld.global.nc.cs (read-only descriptor path + evict-first), via inline PTX.
//
// Per row n (N=65536):
//   m = max_k |dot(x[n,k,:], y[n,0,:])|   (K=1024, D=4)
//   if m > 0.9999999 -> m = 1.0
//   d[n] = 2*acos(m)   (acos monotone => min_k 2*acos == 2*acos(max_k))
// out = sum(d) / N
//
// Inputs: d_in[0]=y (N,1,4) f32, d_in[1]=w_y (UNUSED), d_in[2]=x (N,K,4) f32.
// Output: 1 f32 scalar.
//
// Policy matrix measured so far (same structure):
//   .cs        148.2 us  DRAM 90.7%   <- champion
//   .lu        149.8 us  DRAM 88.9%
//   .nc        151.6 us  DRAM 88.3%
//   .nc.cs     this round
// Revert to .cs champion if this is not faster.

#define N_ROWS   65536
#define K_DIM    1024
#define WARPS_PER_BLOCK 8
#define THREADS  (WARPS_PER_BLOCK * 32)       // 256
#define NBLOCKS  (N_ROWS / WARPS_PER_BLOCK)   // 8192

#define FX_SCALE   16777216.0   // 2^24
#define CNT_SHIFT  50
#define FX_MASK    ((1ULL << CNT_SHIFT) - 1ULL)

__device__ unsigned long long g_acc = 0ULL;   // packed {counter, fixed-point sum}

__device__ __forceinline__ float4 ldg_nc_cs_f4(const float4* p) {
    float4 v;
    asm volatile("ld.global.nc.cs.v4.f32 {%0, %1, %2, %3}, [%4];"
                 : "=f"(v.x), "=f"(v.y), "=f"(v.z), "=f"(v.w)
                 : "l"(p));
    return v;
}

__global__ __launch_bounds__(THREADS)
void fused_kernel(const float* __restrict__ y,
                  const float* __restrict__ x,
                  float* __restrict__ out)
{
    const int warp_in_blk = threadIdx.x >> 5;
    const int lane        = threadIdx.x & 31;
    const int n           = blockIdx.x * WARPS_PER_BLOCK + warp_in_blk;

    // y0 for this row: all lanes of the warp read the same float4 (broadcast)
    const float4 y0 = reinterpret_cast<const float4*>(y)[n];

    const float4* xp = reinterpret_cast<const float4*>(x) + (size_t)n * K_DIM;

    float m = 0.0f;
    #pragma unroll 8
    for (int i = 0; i < K_DIM / 32; ++i) {
        float4 v = ldg_nc_cs_f4(&xp[lane + 32 * i]);   // nc path + evict-first
        float dot = fabsf(v.x * y0.x + v.y * y0.y + v.z * y0.z + v.w * y0.w);
        m = fmaxf(m, dot);
    }

    // warp max-reduce
    #pragma unroll
    for (int off = 16; off > 0; off >>= 1)
        m = fmaxf(m, __shfl_xor_sync(0xFFFFFFFFu, m, off));

    __shared__ float s_d[WARPS_PER_BLOCK];
    if (lane == 0) {
        if (m > 0.9999999f) m = 1.0f;
        s_d[warp_in_blk] = 2.0f * acosf(m);
    }
    __syncthreads();

    if (threadIdx.x == 0) {
        float t = 0.0f;
        #pragma unroll
        for (int i = 0; i < WARPS_PER_BLOCK; ++i) t += s_d[i];

        // Fixed-point contribution (exact f32 -> fixed via double), packed
        // with a completion count in the high bits. One atomic finalizes:
        // integer adds are associative => deterministic across arrivals.
        unsigned long long fx  = (unsigned long long)((double)t * FX_SCALE + 0.5);
        unsigned long long pkt = fx + (1ULL << CNT_SHIFT);
        unsigned long long old = atomicAdd(&g_acc, pkt);

        if ((old >> CNT_SHIFT) == (unsigned long long)(NBLOCKS - 1)) {
            // last block: total = old + own packet (no loads, no fences)
            unsigned long long total = (old + pkt) & FX_MASK;
            out[0] = (float)((double)total * (1.0 / FX_SCALE) / (double)N_ROWS);
            g_acc = 0ULL;                     // reset for next graph replay
        }
    }
}

extern "C" void kernel_launch(void* const* d_in, const int* in_sizes, int n_in,
                              void* d_out, int out_size)
{
    const float* y = (const float*)d_in[0];
    // d_in[1] = w_y : unused by the reference reduction
    const float* x = (const float*)d_in[2];
    float* out = (float*)d_out;

    fused_kernel<<<NBLOCKS, THREADS>>>(y, x, out);
}

// round 14
// speedup vs baseline: 1.0132x; 1.0132x over previous
#include <cuda_runtime.h>

// SinkhornEvalKBestAbs — FINAL champion kernel (locked).
//
// Per row n (N=65536):
//   m = max_k |dot(x[n,k,:], y[n,0,:])|   (K=1024, D=4)
//   if m > 0.9999999 -> m = 1.0   (cost >= 0 so the LOWER clamp is dead)
//   d[n] = 2*acos(m)   (acos monotone decreasing => min_k 2*acos == 2*acos(max_k)
//                       -> exactly ONE acosf per row instead of 1024)
// out = sum(d) / N
//
// Inputs: d_in[0]=y (N,1,4) f32, d_in[1]=w_y (UNUSED — never read),
//         d_in[2]=x (N,K,4) f32. Output: 1 f32 scalar.
//
// Complete measured ladder (GB300 sm_103a; compulsory traffic 1.074 GB):
//   R1  two-kernel, __ldg ......................... 152.0 us
//   R2  256thr x 8192, __ldcs, ticket tail ........ 148.2 us, DRAM 90.3%
//   R3  persistent 1184 blocks .................... 153.6 us  (regression)
//   R4  2-level ticket ............................ 150.1 us  (neutral-)
//   R5  __ldg stream .............................. 151.6 us  (regression)
//   R7  packed-atomic tail ........................ 149.6 us  (neutral)
//   R8  512thr x 4096 ............................. 149.5 us  (neutral)
//   R9  champion: R2 stream + R7 tail ............. 148.2 us, DRAM 90.7% (7185 GB/s)
//   R10 __ldlu stream ............................. 149.8 us  (neutral-)
//   R11/R12 champion re-benches ................... 149.6 / 149.8 us (noise band)
//   R13 ld.global.nc.cs stream .................... 149.9 us  (neutral)
// => HBM-roofline-bound: 89-91% DRAM, 7.1-7.2 TB/s; fma 5.6%, issue 10%.
//    Floor at achieved bandwidth ~= 149 us == measurement. Search closed.
//
// Design:
//  - warp-per-row: 32 lanes x 32 float4 LDG.128, perfectly coalesced
//    (each block covers 128 KB contiguous), unroll 8 for MLP; __ldcs
//    (evict-first) — measured-best policy for a read-once stream.
//  - warp shuffle max-reduce; single acosf on lane 0.
//  - finalization: ONE packed u64 atomicAdd per block — low 50 bits carry a
//    2^24 fixed-point d-sum (exact f32->fixed via double; block sum <= 8*pi
//    so no overflow: 8192*(2^50+2^30) < 2^63), high bits count completions.
//    Integer adds are associative -> bit-deterministic across arrival order.
//    Last arriving block reconstructs total = old + own packet with zero
//    loads/fences, writes out, resets the accumulator for graph replay.

#define N_ROWS   65536
#define K_DIM    1024
#define WARPS_PER_BLOCK 8
#define THREADS  (WARPS_PER_BLOCK * 32)       // 256
#define NBLOCKS  (N_ROWS / WARPS_PER_BLOCK)   // 8192

#define FX_SCALE   16777216.0   // 2^24
#define CNT_SHIFT  50
#define FX_MASK    ((1ULL << CNT_SHIFT) - 1ULL)

__device__ unsigned long long g_acc = 0ULL;   // packed {counter, fixed-point sum}

__global__ __launch_bounds__(THREADS)
void fused_kernel(const float* __restrict__ y,
                  const float* __restrict__ x,
                  float* __restrict__ out)
{
    const int warp_in_blk = threadIdx.x >> 5;
    const int lane        = threadIdx.x & 31;
    const int n           = blockIdx.x * WARPS_PER_BLOCK + warp_in_blk;

    // y0 for this row: all lanes of the warp read the same float4 (broadcast)
    const float4 y0 = reinterpret_cast<const float4*>(y)[n];

    const float4* xp = reinterpret_cast<const float4*>(x) + (size_t)n * K_DIM;

    float m = 0.0f;
    #pragma unroll 8
    for (int i = 0; i < K_DIM / 32; ++i) {
        float4 v = __ldcs(&xp[lane + 32 * i]);   // streamed once: evict-first
        float dot = fabsf(v.x * y0.x + v.y * y0.y + v.z * y0.z + v.w * y0.w);
        m = fmaxf(m, dot);
    }

    // warp max-reduce
    #pragma unroll
    for (int off = 16; off > 0; off >>= 1)
        m = fmaxf(m, __shfl_xor_sync(0xFFFFFFFFu, m, off));

    __shared__ float s_d[WARPS_PER_BLOCK];
    if (lane == 0) {
        if (m > 0.9999999f) m = 1.0f;
        s_d[warp_in_blk] = 2.0f * acosf(m);
    }
    __syncthreads();

    if (threadIdx.x == 0) {
        float t = 0.0f;
        #pragma unroll
        for (int i = 0; i < WARPS_PER_BLOCK; ++i) t += s_d[i];

        // Fixed-point contribution (exact f32 -> fixed via double), packed
        // with a completion count in the high bits. One atomic finalizes:
        // integer adds are associative => deterministic across arrivals.
        unsigned long long fx  = (unsigned long long)((double)t * FX_SCALE + 0.5);
        unsigned long long pkt = fx + (1ULL << CNT_SHIFT);
        unsigned long long old = atomicAdd(&g_acc, pkt);

        if ((old >> CNT_SHIFT) == (unsigned long long)(NBLOCKS - 1)) {
            // last block: total = old + own packet (no loads, no fences)
            unsigned long long total = (old + pkt) & FX_MASK;
            out[0] = (float)((double)total * (1.0 / FX_SCALE) / (double)N_ROWS);
            g_acc = 0ULL;                     // reset for next graph replay
        }
    }
}

extern "C" void kernel_launch(void* const* d_in, const int* in_sizes, int n_in,
                              void* d_out, int out_size)
{
    const float* y = (const float*)d_in[0];
    // d_in[1] = w_y : unused by the reference reduction
    const float* x = (const float*)d_in[2];
    float* out = (float*)d_out;

    fused_kernel<<<NBLOCKS, THREADS>>>(y, x, out);
}